// round 17
// baseline (speedup 1.0000x reference)
#include <cuda_runtime.h>
#include <math.h>

#define Nn 10000
#define Ee 160000
#define ETOT (Ee + Nn)
#define IND 512
#define Cc 128
#define NCc 40
#define NLAY 4
#define HE 8
#define GR 16
#define KT 16
#define DKk 16

// ------------------------- scratch (device globals; no allocations) ---------
__device__ float g_xall[Nn * 5 * Cc];   // x_all levels 0..4
__device__ float g_q[Nn * Cc];          // PERMUTED head layout (see qkv)
__device__ float g_k[Nn * 4 * Cc];      // PERMUTED, levels 0..3
__device__ float g_v[Nn * 4 * Cc];      // PERMUTED
__device__ int   g_cnt[Nn];             // in-degree incl self loop
__device__ float g_dinv[Nn];
__device__ float g_norm[ETOT];
__device__ int   g_off[Nn + 1];
__device__ int   g_cur[Nn];
__device__ int   g_eid[ETOT];
__device__ float g_en[Nn * Cc];
__device__ float g_plc[Nn * NCc];
__device__ float g_tval[Nn * KT];
__device__ int   g_tidx[Nn * KT];

// ------------------------- 1) h0 = relu(x @ W1 + b1) ------------------------
__global__ __launch_bounds__(256) void gemm1_relu_kernel(
    const float* __restrict__ x, const float* __restrict__ W1,
    const float* __restrict__ b1) {
  __shared__ float xs[32][65];    // xs[k][m], 64 rows
  __shared__ float ws[32][128];
  int m0 = blockIdx.x * 64;
  int tid = threadIdx.x;
  int tc = tid & 15;   // 16 col-groups of 8
  int tr = tid >> 4;   // 16 row-groups of 4
  float acc[4][8];
#pragma unroll
  for (int r = 0; r < 4; r++)
#pragma unroll
    for (int c = 0; c < 8; c++) acc[r][c] = 0.f;

  for (int k0 = 0; k0 < IND; k0 += 32) {
    for (int i = tid; i < 64 * 32; i += 256) {
      int m = i >> 5, k = i & 31;
      int row = m0 + m;
      xs[k][m] = (row < Nn) ? x[row * IND + k0 + k] : 0.f;
    }
    for (int i = tid; i < 32 * 128; i += 256) {
      int k = i >> 7, c = i & 127;
      ws[k][c] = W1[(k0 + k) * Cc + c];
    }
    __syncthreads();
#pragma unroll
    for (int k = 0; k < 32; k++) {
      float xv[4], wv[8];
#pragma unroll
      for (int r = 0; r < 4; r++) xv[r] = xs[k][tr * 4 + r];
#pragma unroll
      for (int c = 0; c < 8; c++) wv[c] = ws[k][tc * 8 + c];
#pragma unroll
      for (int r = 0; r < 4; r++)
#pragma unroll
        for (int c = 0; c < 8; c++) acc[r][c] = fmaf(xv[r], wv[c], acc[r][c]);
    }
    __syncthreads();
  }
#pragma unroll
  for (int r = 0; r < 4; r++) {
    int row = m0 + tr * 4 + r;
    if (row < Nn) {
#pragma unroll
      for (int c = 0; c < 8; c++) {
        int col = tc * 8 + c;
        float v = acc[r][c] + b1[col];
        g_xall[row * 5 * Cc + col] = v > 0.f ? v : 0.f;   // level 0
      }
    }
  }
}

// ------------------------- 2) gcn_norm + CSR build (deterministic) ----------
__global__ void count_kernel(const int* __restrict__ coli) {
  int e = blockIdx.x * blockDim.x + threadIdx.x;
  if (e >= ETOT) return;
  int c = (e < Ee) ? coli[e] : (e - Ee);
  atomicAdd(&g_cnt[c], 1);
}

__global__ void dinv_kernel() {
  int n = blockIdx.x * blockDim.x + threadIdx.x;
  if (n < Nn) g_dinv[n] = 1.0f / sqrtf((float)g_cnt[n]);
}

__global__ void norm_kernel(const int* __restrict__ rowi,
                            const int* __restrict__ coli) {
  int e = blockIdx.x * blockDim.x + threadIdx.x;
  if (e >= ETOT) return;
  if (e < Ee) g_norm[e] = g_dinv[rowi[e]] * g_dinv[coli[e]];
  else { float d = g_dinv[e - Ee]; g_norm[e] = d * d; }
}

// single-block exclusive scan of g_cnt -> g_off (1024 threads, 10 elems each)
__global__ __launch_bounds__(1024) void scan_kernel() {
  __shared__ int ssum[1024];
  int t = threadIdx.x;
  int base = t * 10;
  int loc[10];
  int s = 0;
#pragma unroll
  for (int i = 0; i < 10; i++) {
    int idx = base + i;
    int v = (idx < Nn) ? g_cnt[idx] : 0;
    loc[i] = s;
    s += v;
  }
  ssum[t] = s;
  __syncthreads();
  for (int off = 1; off < 1024; off <<= 1) {
    int v = (t >= off) ? ssum[t - off] : 0;
    __syncthreads();
    ssum[t] += v;
    __syncthreads();
  }
  int pre = (t > 0) ? ssum[t - 1] : 0;
#pragma unroll
  for (int i = 0; i < 10; i++) {
    int idx = base + i;
    if (idx < Nn) g_off[idx] = pre + loc[i];
  }
  if (t == 1023) g_off[Nn] = ssum[1023];
}

__global__ void place_kernel(const int* __restrict__ coli) {
  int e = blockIdx.x * blockDim.x + threadIdx.x;
  if (e >= ETOT) return;
  int c = (e < Ee) ? coli[e] : (e - Ee);
  int pos = atomicAdd(&g_cur[c], 1);
  g_eid[g_off[c] + pos] = e;
}

// canonicalize bucket order: insertion-sort each bucket ascending by edge id.
#define SB(i) sbuf[(i) * 128 + tid]
__global__ __launch_bounds__(128) void sort_bucket_kernel() {
  __shared__ int sbuf[64 * 128];
  int tid = threadIdx.x;
  int n = blockIdx.x * 128 + tid;
  if (n >= Nn) return;
  int s = g_off[n], e2 = g_off[n + 1];
  int len = e2 - s;
  if (len <= 64) {
    for (int i = 0; i < len; i++) SB(i) = g_eid[s + i];
    for (int i = 1; i < len; i++) {
      int key = SB(i);
      int j = i - 1;
      while (j >= 0) {
        int v = SB(j);
        if (v <= key) break;
        SB(j + 1) = v;
        j--;
      }
      SB(j + 1) = key;
    }
    for (int i = 0; i < len; i++) g_eid[s + i] = SB(i);
  } else {
    for (int i = s + 1; i < e2; i++) {
      int key = g_eid[i];
      int j = i - 1;
      while (j >= s && g_eid[j] > key) { g_eid[j + 1] = g_eid[j]; j--; }
      g_eid[j + 1] = key;
    }
  }
}

// ------------------------- 3a) grouped q/k/v per layer ---------------------
// PERMUTED head layout; 4 nodes/block with register-resident weights.
// DOQK=0 (layer 0): only v is ever consumed (attention weights are exactly 1
// for a single level), so q/k stores are skipped. Values identical.
template <int DOQK>
__global__ __launch_bounds__(128) void qkv_kernel(
    const float* __restrict__ Wq, const float* __restrict__ bq,
    const float* __restrict__ Wk, const float* __restrict__ bk,
    const float* __restrict__ Wv, const float* __restrict__ bv, int l) {
  int n0 = blockIdx.x * 4;
  int c = threadIdx.x;
  int g = c >> 3, o = c & 7;
  __shared__ float xs[Cc];
  float wq[8], wk[8], wv[8];
  int base = ((l * GR + g) * 8) * 8 + o;
#pragma unroll
  for (int i = 0; i < 8; i++) {
    if (DOQK) {
      wq[i] = Wq[base + i * 8];
      wk[i] = Wk[base + i * 8];
    }
    wv[i] = Wv[base + i * 8];
  }
  int hh = c >> 4, dd = c & 15;
  int pidx = hh * 16 + (dd & 3) * 4 + (dd >> 2);
  float bqv = DOQK ? bq[l * Cc + c] : 0.f;
  float bkv = DOQK ? bk[l * Cc + c] : 0.f;
  float bvv = bv[l * Cc + c];
#pragma unroll 1
  for (int ni = 0; ni < 4; ni++) {
    int n = n0 + ni;
    if (n >= Nn) break;
    for (int lev = 0; lev <= l; lev++) {
      __syncthreads();
      xs[c] = g_xall[(n * 5 + lev) * Cc + c];
      __syncthreads();
      float xg[8];
#pragma unroll
      for (int i = 0; i < 8; i++) xg[i] = xs[g * 8 + i];
      float sv = bvv;
#pragma unroll
      for (int i = 0; i < 8; i++) sv = fmaf(xg[i], wv[i], sv);
      g_v[(n * 4 + lev) * Cc + pidx] = sv;
      if (DOQK) {
        float sk = bkv;
#pragma unroll
        for (int i = 0; i < 8; i++) sk = fmaf(xg[i], wk[i], sk);
        g_k[(n * 4 + lev) * Cc + pidx] = sk;
        if (lev == l) {
          float sq = bqv;
#pragma unroll
          for (int i = 0; i < 8; i++) sq = fmaf(xg[i], wq[i], sq);
          g_q[n * Cc + pidx] = sq;
        }
      }
    }
  }
}

// ------------------------- 3b) deterministic attention gather --------------
// One WARP per node; float4 permuted q/k/v; shfl tree bit-identical to the
// original xor8/4/2/1 butterfly. k/v/norm preloaded per iteration (MLP).
template <int NLEV>
__device__ __forceinline__ float edge_weight_v(const float4* __restrict__ k4,
                                               float nrm, float4 q4,
                                               float* __restrict__ sc) {
  const unsigned FULL = 0xffffffffu;
  float mx = -1e30f;
#pragma unroll
  for (int lev = 0; lev < NLEV; lev++) {
    float tx = q4.x * k4[lev].x, ty = q4.y * k4[lev].y;
    float tz = q4.z * k4[lev].z, tw = q4.w * k4[lev].w;
    float B = (tx + tz) + (ty + tw);
    float C = B + __shfl_xor_sync(FULL, B, 2);
    float D = C + __shfl_xor_sync(FULL, C, 1);
    D *= 0.25f;   // 1/sqrt(DK)
    sc[lev] = D;
    mx = fmaxf(mx, D);
  }
  float den = 0.f;
#pragma unroll
  for (int lev = 0; lev < NLEV; lev++) {
    sc[lev] = expf(sc[lev] - mx);
    den += sc[lev];
  }
  return nrm / den;
}

template <int NLEV>
__global__ __launch_bounds__(128) void attn_gather_kernel(
    const int* __restrict__ rowi, int l) {
  int warp = threadIdx.x >> 5, lane = threadIdx.x & 31;
  int c = blockIdx.x * 4 + warp;
  if (c >= Nn) return;
  float4 q4 = ((const float4*)g_q)[c * (Cc / 4) + lane];
  int s = g_off[c], e2 = g_off[c + 1];
  float4 acc = make_float4(0.f, 0.f, 0.f, 0.f);
  int p = s;
  for (; p + 1 < e2; p += 2) {
    int ea = g_eid[p];
    int eb = g_eid[p + 1];
    int ra = (ea < Ee) ? rowi[ea] : (ea - Ee);
    int rb = (eb < Ee) ? rowi[eb] : (eb - Ee);
    float na = g_norm[ea], nb = g_norm[eb];
    // all loads up front (max MLP); weight chains then run on registers
    float4 va[NLEV], vb[NLEV], ka[NLEV], kb[NLEV];
#pragma unroll
    for (int lev = 0; lev < NLEV; lev++) {
      va[lev] = ((const float4*)g_v)[(ra * 4 + lev) * (Cc / 4) + lane];
      vb[lev] = ((const float4*)g_v)[(rb * 4 + lev) * (Cc / 4) + lane];
      ka[lev] = ((const float4*)g_k)[(ra * 4 + lev) * (Cc / 4) + lane];
      kb[lev] = ((const float4*)g_k)[(rb * 4 + lev) * (Cc / 4) + lane];
    }
    float sca[NLEV], scb[NLEV];
    float wa = edge_weight_v<NLEV>(ka, na, q4, sca);
    float wb = edge_weight_v<NLEV>(kb, nb, q4, scb);
#pragma unroll
    for (int lev = 0; lev < NLEV; lev++) {
      float wl = sca[lev] * wa;
      acc.x = fmaf(wl, va[lev].x, acc.x);
      acc.y = fmaf(wl, va[lev].y, acc.y);
      acc.z = fmaf(wl, va[lev].z, acc.z);
      acc.w = fmaf(wl, va[lev].w, acc.w);
    }
#pragma unroll
    for (int lev = 0; lev < NLEV; lev++) {
      float wl = scb[lev] * wb;
      acc.x = fmaf(wl, vb[lev].x, acc.x);
      acc.y = fmaf(wl, vb[lev].y, acc.y);
      acc.z = fmaf(wl, vb[lev].z, acc.z);
      acc.w = fmaf(wl, vb[lev].w, acc.w);
    }
  }
  if (p < e2) {
    int e = g_eid[p];
    int r = (e < Ee) ? rowi[e] : (e - Ee);
    float nrm = g_norm[e];
    float4 vv[NLEV], kk[NLEV];
#pragma unroll
    for (int lev = 0; lev < NLEV; lev++) {
      vv[lev] = ((const float4*)g_v)[(r * 4 + lev) * (Cc / 4) + lane];
      kk[lev] = ((const float4*)g_k)[(r * 4 + lev) * (Cc / 4) + lane];
    }
    float sc[NLEV];
    float w = edge_weight_v<NLEV>(kk, nrm, q4, sc);
#pragma unroll
    for (int lev = 0; lev < NLEV; lev++) {
      float wl = sc[lev] * w;
      acc.x = fmaf(wl, vv[lev].x, acc.x);
      acc.y = fmaf(wl, vv[lev].y, acc.y);
      acc.z = fmaf(wl, vv[lev].z, acc.z);
      acc.w = fmaf(wl, vv[lev].w, acc.w);
    }
  }
  int h = lane >> 2, g = lane & 3;
  float* out = g_xall + (size_t)(c * 5 + l + 1) * Cc + h * 16 + g;
  out[0]  = acc.x > 0.f ? acc.x : 0.f;
  out[4]  = acc.y > 0.f ? acc.y : 0.f;
  out[8]  = acc.z > 0.f ? acc.z : 0.f;
  out[12] = acc.w > 0.f ? acc.w : 0.f;
}

// Layer-0 attention: softmax over ONE level is exactly 1.0 (expf(0)=1, den=1,
// nrm/1=nrm, 1*nrm=nrm), so msg = sum nrm*v — bit-identical to the full path
// with all dot/shfl/exp work removed.
__global__ __launch_bounds__(128) void attn_gather0_kernel(
    const int* __restrict__ rowi) {
  int warp = threadIdx.x >> 5, lane = threadIdx.x & 31;
  int c = blockIdx.x * 4 + warp;
  if (c >= Nn) return;
  int s = g_off[c], e2 = g_off[c + 1];
  float4 acc = make_float4(0.f, 0.f, 0.f, 0.f);
  int p = s;
  for (; p + 1 < e2; p += 2) {
    int ea = g_eid[p];
    int eb = g_eid[p + 1];
    int ra = (ea < Ee) ? rowi[ea] : (ea - Ee);
    int rb = (eb < Ee) ? rowi[eb] : (eb - Ee);
    float na = g_norm[ea], nb = g_norm[eb];
    float4 va = ((const float4*)g_v)[(ra * 4) * (Cc / 4) + lane];
    float4 vb = ((const float4*)g_v)[(rb * 4) * (Cc / 4) + lane];
    acc.x = fmaf(na, va.x, acc.x);
    acc.y = fmaf(na, va.y, acc.y);
    acc.z = fmaf(na, va.z, acc.z);
    acc.w = fmaf(na, va.w, acc.w);
    acc.x = fmaf(nb, vb.x, acc.x);
    acc.y = fmaf(nb, vb.y, acc.y);
    acc.z = fmaf(nb, vb.z, acc.z);
    acc.w = fmaf(nb, vb.w, acc.w);
  }
  if (p < e2) {
    int e = g_eid[p];
    int r = (e < Ee) ? rowi[e] : (e - Ee);
    float nrm = g_norm[e];
    float4 vv = ((const float4*)g_v)[(r * 4) * (Cc / 4) + lane];
    acc.x = fmaf(nrm, vv.x, acc.x);
    acc.y = fmaf(nrm, vv.y, acc.y);
    acc.z = fmaf(nrm, vv.z, acc.z);
    acc.w = fmaf(nrm, vv.w, acc.w);
  }
  int h = lane >> 2, g = lane & 3;
  float* out = g_xall + (size_t)(c * 5 + 1) * Cc + h * 16 + g;
  out[0]  = acc.x > 0.f ? acc.x : 0.f;
  out[4]  = acc.y > 0.f ? acc.y : 0.f;
  out[8]  = acc.z > 0.f ? acc.z : 0.f;
  out[12] = acc.w > 0.f ? acc.w : 0.f;
}

// ------------------------- 4) emb out + L2 normalize -----------------------
__global__ __launch_bounds__(128) void emb_norm_kernel(float* __restrict__ out_emb) {
  int n = blockIdx.x;
  int c = threadIdx.x;
  float v = g_xall[(n * 5 + 4) * Cc + c];
  out_emb[n * Cc + c] = v;
  float ss = v * v;
#pragma unroll
  for (int off = 16; off; off >>= 1) ss += __shfl_down_sync(0xffffffffu, ss, off);
  __shared__ float ws[4];
  if ((c & 31) == 0) ws[c >> 5] = ss;
  __syncthreads();
  float tot = ws[0] + ws[1] + ws[2] + ws[3];
  float nrm = fmaxf(sqrtf(tot), 1e-8f);
  g_en[n * Cc + c] = v / nrm;
}

// ------------------------- 5) p_lc = log_softmax(emb@W2+b2) ----------------
__global__ __launch_bounds__(128) void plc_kernel(const float* __restrict__ W2,
                                                  const float* __restrict__ b2) {
  int n = blockIdx.x;
  int t = threadIdx.x;
  __shared__ float xr[Cc];
  __shared__ float lg[NCc];
  __shared__ float red[2];
  xr[t] = g_xall[(n * 5 + 4) * Cc + t];
  __syncthreads();
  if (t < NCc) {
    float s = b2[t];
    for (int k = 0; k < Cc; k++) s = fmaf(xr[k], W2[k * NCc + t], s);
    lg[t] = s;
  }
  __syncthreads();
  if (t == 0) {
    float mx = lg[0];
    for (int i = 1; i < NCc; i++) mx = fmaxf(mx, lg[i]);
    float s = 0.f;
    for (int i = 0; i < NCc; i++) s += expf(lg[i] - mx);
    red[0] = mx;
    red[1] = logf(s);
  }
  __syncthreads();
  if (t < NCc) g_plc[n * NCc + t] = lg[t] - red[0] - red[1];
}

// ------------------------- 6) fused sim = en@en^T + top-16 -----------------
// v9: contiguous-lane column ownership (lane owns cols lane*8..lane*8+7) so
// cv loads are 2x LDS.128/k. Same per-(row,col) FMA chain and exact selection
// -> bit-identical output. CPAD=260 keeps every k row 16B-aligned.
#define SROWS 80     // rows per block (16 warps x 5 rows)
#define RPW 5
#define SGRID 125    // 125 * 80 = 10000 exactly; single wave on 148 SMs
#define STHREADS 512
#define SCOLS 256
#define CPAD 260
#define CAP 80
#define SIM_SMEM ((128 * CPAD + SROWS * Cc + SROWS * CAP) * 4 + SROWS * CAP * 4 + SROWS * 8)

// exact tie-aware top-16 selection of buf[0..n) into buf[0..15]; updates thr/cnt
__device__ __noinline__ void refresh_row(float* __restrict__ v,
                                         int* __restrict__ ix,
                                         float* __restrict__ thr,
                                         int* __restrict__ cnt,
                                         int rl, int lane) {
  const unsigned FULL = 0xffffffffu;
  int n = cnt[rl];
#pragma unroll 1
  for (int pick = 0; pick < KT; pick++) {
    float mv = -3.4e38f; int mi = 0x7fffffff; int mp = pick;
    for (int s = pick + lane; s < n; s += 32) {
      float vv = v[s]; int ii = ix[s];
      if (vv > mv || (vv == mv && ii < mi)) { mv = vv; mi = ii; mp = s; }
    }
#pragma unroll
    for (int off = 16; off; off >>= 1) {
      float ov = __shfl_down_sync(FULL, mv, off);
      int oi = __shfl_down_sync(FULL, mi, off);
      int op = __shfl_down_sync(FULL, mp, off);
      if (ov > mv || (ov == mv && oi < mi)) { mv = ov; mi = oi; mp = op; }
    }
    mp = __shfl_sync(FULL, mp, 0);
    mv = __shfl_sync(FULL, mv, 0);
    mi = __shfl_sync(FULL, mi, 0);
    if (lane == 0 && mp != pick) {
      float tv = v[pick]; int ti = ix[pick];
      v[pick] = mv; ix[pick] = mi;
      v[mp] = tv; ix[mp] = ti;
    }
    __syncwarp();
  }
  if (lane == 0) { thr[rl] = v[KT - 1]; cnt[rl] = KT; }
  __syncwarp();
}

// one ballot-insert step; lane owns cols j0 + lane*8 + colofs
#define COLLECT_ONE(val, colofs)                                          \
  do {                                                                    \
    float v_ = (val);                                                     \
    int colx_ = j0 + lane * 8 + (colofs);                                 \
    bool p_ = (colx_ < Nn) && (v_ >= thr_r);                              \
    unsigned mask_ = __ballot_sync(0xffffffffu, p_);                      \
    if (mask_) {                                                          \
      int base_ = cnt[rl];                                                \
      if (p_) {                                                           \
        int pos_ = base_ + __popc(mask_ & ((1u << lane) - 1u));           \
        bv[pos_] = v_;                                                    \
        bi[pos_] = colx_;                                                 \
      }                                                                   \
      int nb_ = base_ + __popc(mask_);                                    \
      if (lane == 0) cnt[rl] = nb_;                                       \
      __syncwarp();                                                       \
      if (nb_ >= CAP - 32) {                                              \
        refresh_row(bv, bi, thr, cnt, rl, lane);                          \
        thr_r = thr[rl];                                                  \
      }                                                                   \
    }                                                                     \
  } while (0)

// candidates for one row; rowmax guard (bit-identical fast path)
__device__ __noinline__ void collect_row(int rl, int j0, int lane,
                                         float4 va, float4 vb,
                                         float* __restrict__ bv,
                                         int* __restrict__ bi,
                                         float* __restrict__ thr,
                                         int* __restrict__ cnt) {
  float thr_r = thr[rl];
  float m0 = fmaxf(fmaxf(va.x, va.y), fmaxf(va.z, va.w));
  float m1 = fmaxf(fmaxf(vb.x, vb.y), fmaxf(vb.z, vb.w));
  float rmax = fmaxf(m0, m1);
  unsigned any = __ballot_sync(0xffffffffu, rmax >= thr_r);
  if (!any) return;
  COLLECT_ONE(va.x, 0);
  COLLECT_ONE(va.y, 1);
  COLLECT_ONE(va.z, 2);
  COLLECT_ONE(va.w, 3);
  COLLECT_ONE(vb.x, 4);
  COLLECT_ONE(vb.y, 5);
  COLLECT_ONE(vb.z, 6);
  COLLECT_ONE(vb.w, 7);
}

__global__ __launch_bounds__(STHREADS) void sim_topk_kernel() {
  extern __shared__ float sm[];
  float* colsT = sm;                              // [128][CPAD]
  float* rows  = sm + 128 * CPAD;                 // [SROWS][128]
  float* bufv  = rows + SROWS * Cc;               // [SROWS][CAP]
  int*   bufi  = (int*)(bufv + SROWS * CAP);      // [SROWS][CAP]
  float* thr   = (float*)(bufi + SROWS * CAP);    // [SROWS]
  int*   cnt   = (int*)(thr + SROWS);             // [SROWS]

  int r0 = blockIdx.x * SROWS;
  int tid = threadIdx.x;
  int warp = tid >> 5, lane = tid & 31;
  int rlbase = warp * RPW;

  for (int i = tid; i < SROWS * Cc; i += STHREADS) {
    int row = r0 + (i >> 7);
    rows[i] = (row < Nn) ? g_en[row * Cc + (i & 127)] : 0.f;
  }
  if (tid < SROWS) { thr[tid] = -3.3e38f; cnt[tid] = 0; }
  __syncthreads();

  int rlocal = lane >> 3;   // 0..3
  int kc = lane & 7;        // 0..7

  for (int j0 = 0; j0 < Nn; j0 += SCOLS) {
    // ---- fill colsT[k][j] (transposed, coalesced float4 loads) ----
#pragma unroll 4
    for (int it = 0; it < 16; it++) {
      int u = it * 16 + warp;
      int rowgrp = u >> 2, kq = u & 3;
      int j = rowgrp * 4 + rlocal;    // 0..255
      int k4 = kq * 8 + kc;           // 0..31
      int col = j0 + j;
      float4 val = make_float4(0.f, 0.f, 0.f, 0.f);
      if (col < Nn) val = ((const float4*)g_en)[col * (Cc / 4) + k4];
      colsT[(k4 * 4 + 0) * CPAD + j] = val.x;
      colsT[(k4 * 4 + 1) * CPAD + j] = val.y;
      colsT[(k4 * 4 + 2) * CPAD + j] = val.z;
      colsT[(k4 * 4 + 3) * CPAD + j] = val.w;
    }
    __syncthreads();

    // ---- packed f32x2 GEMM; cv via 2x LDS.128, rows k-chunked float4 ----
    unsigned long long acc[RPW][4];
#pragma unroll
    for (int r = 0; r < RPW; r++)
#pragma unroll
      for (int c2 = 0; c2 < 4; c2++) acc[r][c2] = 0ULL;

    const float* rowp = rows + rlbase * Cc;
#pragma unroll 2
    for (int k0 = 0; k0 < Cc; k0 += 4) {
      float4 rv4[RPW];
#pragma unroll
      for (int r = 0; r < RPW; r++)
        rv4[r] = *(const float4*)(rowp + r * Cc + k0);
#pragma unroll
      for (int kk = 0; kk < 4; kk++) {
        int k = k0 + kk;
        const float* cb = colsT + k * CPAD + lane * 8;
        ulonglong2 cva = *(const ulonglong2*)(cb);
        ulonglong2 cvb = *(const ulonglong2*)(cb + 4);
        unsigned long long cv[4] = {cva.x, cva.y, cvb.x, cvb.y};
#pragma unroll
        for (int r = 0; r < RPW; r++) {
          float rv = (kk == 0) ? rv4[r].x
                   : (kk == 1) ? rv4[r].y
                   : (kk == 2) ? rv4[r].z : rv4[r].w;
          unsigned long long rv2;
          asm("mov.b64 %0, {%1, %1};" : "=l"(rv2) : "f"(rv));
#pragma unroll
          for (int c2 = 0; c2 < 4; c2++)
            asm("fma.rn.f32x2 %0, %1, %2, %0;"
                : "+l"(acc[r][c2]) : "l"(rv2), "l"(cv[c2]));
        }
      }
    }

    // ---- threshold-buffer candidate collection (acc constant-indexed) ----
#pragma unroll
    for (int r = 0; r < RPW; r++) {
      int rl = rlbase + r;
      float4 va, vb;
      asm("mov.b64 {%0, %1}, %2;" : "=f"(va.x), "=f"(va.y) : "l"(acc[r][0]));
      asm("mov.b64 {%0, %1}, %2;" : "=f"(va.z), "=f"(va.w) : "l"(acc[r][1]));
      asm("mov.b64 {%0, %1}, %2;" : "=f"(vb.x), "=f"(vb.y) : "l"(acc[r][2]));
      asm("mov.b64 {%0, %1}, %2;" : "=f"(vb.z), "=f"(vb.w) : "l"(acc[r][3]));
      collect_row(rl, j0, lane, va, vb,
                  bufv + rl * CAP, bufi + rl * CAP, thr, cnt);
    }
    __syncthreads();
  }

  // ---- final exact selection + output ----
#pragma unroll 1
  for (int r = 0; r < RPW; r++) {
    int rl = rlbase + r;
    int grow = r0 + rl;
    if (grow >= Nn) continue;
    refresh_row(bufv + rl * CAP, bufi + rl * CAP, thr, cnt, rl, lane);
    if (lane < KT) {
      g_tval[grow * KT + lane] = bufv[rl * CAP + lane];
      g_tidx[grow * KT + lane] = bufi[rl * CAP + lane];
    }
  }
}

// ------------------------- 7) p_sim + final combine (deterministic) --------
__global__ __launch_bounds__(64) void psim_final_kernel(
    const int* __restrict__ y, float* __restrict__ out_final) {
  int n = blockIdx.x;
  int t = threadIdx.x;
  __shared__ float ex[KT];
  __shared__ int cls[KT];
  __shared__ float acc[NCc];
  __shared__ float red[2];
  if (t < KT) {
    ex[t] = expf(g_tval[n * KT + t]);
    cls[t] = y[g_tidx[n * KT + t]];
  }
  __syncthreads();
  if (t < NCc) {
    float s = 0.f;
    for (int j = 0; j < KT; j++)
      if (cls[j] == t) s += ex[j];
    acc[t] = s;
  }
  __syncthreads();
  if (t == 0) {
    float mx = acc[0];
    for (int i = 1; i < NCc; i++) mx = fmaxf(mx, acc[i]);
    float s = 0.f;
    for (int i = 0; i < NCc; i++) s += expf(acc[i] - mx);
    red[0] = mx;
    red[1] = logf(s);
  }
  __syncthreads();
  if (t < NCc)
    out_final[n * NCc + t] =
        0.5f * g_plc[n * NCc + t] + 0.5f * (acc[t] - red[0] - red[1]);
}

// ------------------------- host launch --------------------------------------
extern "C" void kernel_launch(void* const* d_in, const int* in_sizes, int n_in,
                              void* d_out, int out_size) {
  (void)in_sizes; (void)n_in; (void)out_size;
  const float* x  = (const float*)d_in[0];
  const float* W1 = (const float*)d_in[1];
  const float* b1 = (const float*)d_in[2];
  const float* Wq = (const float*)d_in[3];
  const float* bq = (const float*)d_in[4];
  const float* Wk = (const float*)d_in[5];
  const float* bk = (const float*)d_in[6];
  const float* Wv = (const float*)d_in[7];
  const float* bv = (const float*)d_in[8];
  const float* W2 = (const float*)d_in[9];
  const float* b2 = (const float*)d_in[10];
  const int* ei   = (const int*)d_in[11];
  const int* y    = (const int*)d_in[12];
  const int* rowi = ei;
  const int* coli = ei + Ee;
  float* out_final = (float*)d_out;
  float* out_emb   = (float*)d_out + (size_t)Nn * NCc;

  void* cntp = 0; cudaGetSymbolAddress(&cntp, g_cnt);
  void* curp = 0; cudaGetSymbolAddress(&curp, g_cur);
  cudaFuncSetAttribute(sim_topk_kernel,
                       cudaFuncAttributeMaxDynamicSharedMemorySize, SIM_SMEM);

  cudaMemsetAsync(cntp, 0, Nn * sizeof(int), 0);
  cudaMemsetAsync(curp, 0, Nn * sizeof(int), 0);
  gemm1_relu_kernel<<<(Nn + 63) / 64, 256>>>(x, W1, b1);
  count_kernel<<<(ETOT + 255) / 256, 256>>>(coli);
  dinv_kernel<<<(Nn + 255) / 256, 256>>>();
  norm_kernel<<<(ETOT + 255) / 256, 256>>>(rowi, coli);
  scan_kernel<<<1, 1024>>>();
  place_kernel<<<(ETOT + 255) / 256, 256>>>(coli);
  sort_bucket_kernel<<<(Nn + 127) / 128, 128>>>();

  for (int l = 0; l < NLAY; l++) {
    if (l == 0) {
      qkv_kernel<0><<<(Nn + 3) / 4, 128>>>(Wq, bq, Wk, bk, Wv, bv, l);
      attn_gather0_kernel<<<Nn / 4, 128>>>(rowi);
    } else {
      qkv_kernel<1><<<(Nn + 3) / 4, 128>>>(Wq, bq, Wk, bk, Wv, bv, l);
      switch (l) {
        case 1: attn_gather_kernel<2><<<Nn / 4, 128>>>(rowi, l); break;
        case 2: attn_gather_kernel<3><<<Nn / 4, 128>>>(rowi, l); break;
        default: attn_gather_kernel<4><<<Nn / 4, 128>>>(rowi, l); break;
      }
    }
  }

  emb_norm_kernel<<<Nn, 128>>>(out_emb);
  plc_kernel<<<Nn, 128>>>(W2, b2);
  sim_topk_kernel<<<SGRID, STHREADS, SIM_SMEM>>>();
  psim_final_kernel<<<Nn, 64>>>(y, out_final);
}